// round 1
// baseline (speedup 1.0000x reference)
#include <cuda_runtime.h>
#include <math.h>

// Problem constants
#define BB 4
#define SS 2048
#define DD 1024
#define HH 16
#define DK 64
#define MM (BB * SS)   // 8192 rows

// Scratch (device globals; allocations are forbidden)
__device__ float g_Q[(size_t)BB * SS * DD];
__device__ float g_K[(size_t)BB * SS * DD];
__device__ float g_V[(size_t)BB * SS * DD];
__device__ float g_C[(size_t)BB * SS * DD];

// ---------------------------------------------------------------------------
// Tiled GEMM:  Y = X @ W^T + bias
//   X: [M, 1024] row-major, W: [N, 1024] row-major (nn.Linear weight)
//   BM=BN=64, BK=16, 256 threads, 4x4 micro-tile per thread.
//   headLayout=1: scatter Y[m, n] into [B, H, S, DK] layout for attention.
// ---------------------------------------------------------------------------
__global__ void __launch_bounds__(256) gemm64(const float* __restrict__ X,
                                              const float* __restrict__ W,
                                              const float* __restrict__ bias,
                                              float* __restrict__ Y,
                                              int headLayout)
{
    __shared__ float At[16][68];   // k-major (transposed) A tile, pad 68
    __shared__ float Bt[16][68];   // k-major (transposed) B tile

    const int tid  = threadIdx.x;
    const int tx   = tid & 15;     // 0..15 -> n micro
    const int ty   = tid >> 4;     // 0..15 -> m micro
    const int m0   = blockIdx.x * 64;
    const int n0   = blockIdx.y * 64;
    const int lrow = tid >> 2;        // 0..63  loader row
    const int lcol = (tid & 3) << 2;  // 0,4,8,12 loader k-offset

    const float* Ap = X + (size_t)(m0 + lrow) * DD + lcol;
    const float* Bp = W + (size_t)(n0 + lrow) * DD + lcol;

    float acc[4][4];
#pragma unroll
    for (int u = 0; u < 4; u++)
#pragma unroll
        for (int v = 0; v < 4; v++) acc[u][v] = 0.f;

    for (int k0 = 0; k0 < DD; k0 += 16) {
        float4 av = *(const float4*)(Ap + k0);
        float4 bv = *(const float4*)(Bp + k0);
        At[lcol + 0][lrow] = av.x;
        At[lcol + 1][lrow] = av.y;
        At[lcol + 2][lrow] = av.z;
        At[lcol + 3][lrow] = av.w;
        Bt[lcol + 0][lrow] = bv.x;
        Bt[lcol + 1][lrow] = bv.y;
        Bt[lcol + 2][lrow] = bv.z;
        Bt[lcol + 3][lrow] = bv.w;
        __syncthreads();
#pragma unroll
        for (int kk = 0; kk < 16; kk++) {
            float4 a4 = *(const float4*)&At[kk][ty << 2];
            float4 b4 = *(const float4*)&Bt[kk][tx << 2];
            float ar[4] = {a4.x, a4.y, a4.z, a4.w};
            float br[4] = {b4.x, b4.y, b4.z, b4.w};
#pragma unroll
            for (int u = 0; u < 4; u++)
#pragma unroll
                for (int v = 0; v < 4; v++) acc[u][v] += ar[u] * br[v];
        }
        __syncthreads();
    }

    float bvals[4];
#pragma unroll
    for (int v = 0; v < 4; v++) bvals[v] = bias[n0 + (tx << 2) + v];

    if (headLayout) {
        // n0 is a multiple of 64 -> whole block lies in one head h
        const int h = n0 >> 6;
#pragma unroll
        for (int u = 0; u < 4; u++) {
            const int m = m0 + (ty << 2) + u;
            const int b = m / SS;
            const int s = m - b * SS;
            float* dst = Y + (((size_t)b * HH + h) * SS + s) * DK + (tx << 2);
#pragma unroll
            for (int v = 0; v < 4; v++) dst[v] = acc[u][v] + bvals[v];
        }
    } else {
#pragma unroll
        for (int u = 0; u < 4; u++) {
            const int m = m0 + (ty << 2) + u;
            float* dst = Y + (size_t)m * DD + n0 + (tx << 2);
#pragma unroll
            for (int v = 0; v < 4; v++) dst[v] = acc[u][v] + bvals[v];
        }
    }
}

// ---------------------------------------------------------------------------
// Flash attention, fp32.
//   Q,K,V in [B*H, S, DK] layout. One block = one (bh, 64-row Q tile).
//   256 threads, 4x4 micro-tiles over 64x64 score / output tiles.
//   Writes concat layout [B, S, D] (head h occupies cols h*64..h*64+63).
// ---------------------------------------------------------------------------
__global__ void __launch_bounds__(256) attn64(const float* __restrict__ Q,
                                              const float* __restrict__ K,
                                              const float* __restrict__ V,
                                              float* __restrict__ C)
{
    extern __shared__ float sm[];
    float* Qt = sm;              // [64][68]  d-major (Qt[d][i])
    float* Kt = Qt + 64 * 68;    // [64][68]  d-major (Kt[d][j])
    float* Pt = Kt + 64 * 68;    // [64][68]  k-major (Pt[k][i])
    float* Vs = Pt + 64 * 68;    // [64][64]  natural (Vs[k][j])

    const int tid  = threadIdx.x;
    const int tx   = tid & 15;
    const int ty   = tid >> 4;
    const int lrow = tid >> 2;        // 0..63
    const int lcol = (tid & 3) << 2;  // 0,4,8,12  (x4 passes cover 64 cols? no:
                                      //  each row loaded by 4 threads x 4 floats = 16; need 4 passes)
    const int bh = blockIdx.y;        // 0..63
    const int q0 = blockIdx.x * 64;

    const float* Qb = Q + ((size_t)bh * SS + q0) * DK;
    const float* Kb = K + (size_t)bh * SS * DK;
    const float* Vb = V + (size_t)bh * SS * DK;

    // Load Q tile transposed: Qt[d][i]
#pragma unroll
    for (int p = 0; p < 4; p++) {
        const int c = lcol + p * 16;     // k/d offset 0..63
        float4 qv = *(const float4*)(Qb + (size_t)lrow * DK + c);
        Qt[(c + 0) * 68 + lrow] = qv.x;
        Qt[(c + 1) * 68 + lrow] = qv.y;
        Qt[(c + 2) * 68 + lrow] = qv.z;
        Qt[(c + 3) * 68 + lrow] = qv.w;
    }

    float o[4][4];
    float m_run[4], l_run[4];
#pragma unroll
    for (int u = 0; u < 4; u++) {
        m_run[u] = -INFINITY;
        l_run[u] = 0.f;
#pragma unroll
        for (int v = 0; v < 4; v++) o[u][v] = 0.f;
    }

    const float scale = 0.125f;  // 1/sqrt(64)

    for (int kt = 0; kt < SS / 64; kt++) {
        __syncthreads();  // prior PV done before overwriting Kt/Vs
        const float* Kp = Kb + (size_t)kt * 64 * DK;
        const float* Vp = Vb + (size_t)kt * 64 * DK;
#pragma unroll
        for (int p = 0; p < 4; p++) {
            const int c = lcol + p * 16;
            float4 kv = *(const float4*)(Kp + (size_t)lrow * DK + c);
            Kt[(c + 0) * 68 + lrow] = kv.x;
            Kt[(c + 1) * 68 + lrow] = kv.y;
            Kt[(c + 2) * 68 + lrow] = kv.z;
            Kt[(c + 3) * 68 + lrow] = kv.w;
            float4 vv = *(const float4*)(Vp + (size_t)lrow * DK + c);
            *(float4*)&Vs[lrow * 64 + c] = vv;
        }
        __syncthreads();

        // scores tile: s[u][v] = sum_d Q[i][d]*K[j][d]
        float s[4][4];
#pragma unroll
        for (int u = 0; u < 4; u++)
#pragma unroll
            for (int v = 0; v < 4; v++) s[u][v] = 0.f;
#pragma unroll 16
        for (int d = 0; d < 64; d++) {
            float4 a4 = *(const float4*)&Qt[d * 68 + (ty << 2)];
            float4 b4 = *(const float4*)&Kt[d * 68 + (tx << 2)];
            float ar[4] = {a4.x, a4.y, a4.z, a4.w};
            float br[4] = {b4.x, b4.y, b4.z, b4.w};
#pragma unroll
            for (int u = 0; u < 4; u++)
#pragma unroll
                for (int v = 0; v < 4; v++) s[u][v] += ar[u] * br[v];
        }

        // online softmax per row (rows split across the 16 tx lanes)
#pragma unroll
        for (int u = 0; u < 4; u++) {
            float mx = s[u][0] * scale;
#pragma unroll
            for (int v = 1; v < 4; v++) mx = fmaxf(mx, s[u][v] * scale);
#pragma unroll
            for (int off = 8; off >= 1; off >>= 1)
                mx = fmaxf(mx, __shfl_xor_sync(0xffffffffu, mx, off, 16));
            const float m_new = fmaxf(m_run[u], mx);
            const float alpha = __expf(m_run[u] - m_new);
            float r = 0.f;
#pragma unroll
            for (int v = 0; v < 4; v++) {
                const float p = __expf(s[u][v] * scale - m_new);
                s[u][v] = p;
                r += p;
            }
#pragma unroll
            for (int off = 8; off >= 1; off >>= 1)
                r += __shfl_xor_sync(0xffffffffu, r, off, 16);
            l_run[u] = l_run[u] * alpha + r;
            m_run[u] = m_new;
#pragma unroll
            for (int v = 0; v < 4; v++) {
                o[u][v] *= alpha;
                // store P~ k-major: Pt[k][i]
                Pt[((tx << 2) + v) * 68 + (ty << 2) + u] = s[u][v];
            }
        }
        __syncthreads();

        // o += P~ @ V
#pragma unroll 16
        for (int k = 0; k < 64; k++) {
            float4 a4 = *(const float4*)&Pt[k * 68 + (ty << 2)];
            float4 b4 = *(const float4*)&Vs[k * 64 + (tx << 2)];
            float ar[4] = {a4.x, a4.y, a4.z, a4.w};
            float br[4] = {b4.x, b4.y, b4.z, b4.w};
#pragma unroll
            for (int u = 0; u < 4; u++)
#pragma unroll
                for (int v = 0; v < 4; v++) o[u][v] += ar[u] * br[v];
        }
    }

    // normalize + write concat [B, S, D]
    const int b = bh / HH;
    const int h = bh - b * HH;
#pragma unroll
    for (int u = 0; u < 4; u++) {
        const float inv = 1.f / l_run[u];
        const int srow = q0 + (ty << 2) + u;
        float* dst = C + ((size_t)b * SS + srow) * DD + h * DK + (tx << 2);
#pragma unroll
        for (int v = 0; v < 4; v++) dst[v] = o[u][v] * inv;
    }
}

// ---------------------------------------------------------------------------
extern "C" void kernel_launch(void* const* d_in, const int* in_sizes, int n_in,
                              void* d_out, int out_size)
{
    const float* q  = (const float*)d_in[0];
    const float* k  = (const float*)d_in[1];
    const float* v  = (const float*)d_in[2];
    const float* Wq = (const float*)d_in[3];
    const float* bq = (const float*)d_in[4];
    const float* Wk = (const float*)d_in[5];
    const float* bk = (const float*)d_in[6];
    const float* Wv = (const float*)d_in[7];
    const float* bv = (const float*)d_in[8];
    const float* Wo = (const float*)d_in[9];
    const float* bo = (const float*)d_in[10];
    float* out = (float*)d_out;

    float *gQ, *gK, *gV, *gC;
    cudaGetSymbolAddress((void**)&gQ, g_Q);
    cudaGetSymbolAddress((void**)&gK, g_K);
    cudaGetSymbolAddress((void**)&gV, g_V);
    cudaGetSymbolAddress((void**)&gC, g_C);

    const int attn_smem = (3 * 64 * 68 + 64 * 64) * (int)sizeof(float);  // 68608 B
    cudaFuncSetAttribute(attn64, cudaFuncAttributeMaxDynamicSharedMemorySize,
                         attn_smem);

    dim3 gemmGrid(MM / 64, DD / 64);  // (128, 16)

    gemm64<<<gemmGrid, 256>>>(q, Wq, bq, gQ, 1);
    gemm64<<<gemmGrid, 256>>>(k, Wk, bk, gK, 1);
    gemm64<<<gemmGrid, 256>>>(v, Wv, bv, gV, 1);

    dim3 attnGrid(SS / 64, BB * HH);  // (32, 64)
    attn64<<<attnGrid, 256, attn_smem>>>(gQ, gK, gV, gC);

    gemm64<<<gemmGrid, 256>>>(gC, Wo, bo, out, 0);
}

// round 2
// speedup vs baseline: 2.7745x; 2.7745x over previous
#include <cuda_runtime.h>
#include <math.h>

#define BBATCH 4
#define SSEQ   2048
#define DDIM   1024
#define HHEADS 16
#define DHEAD  64
#define MROWS  (BBATCH * SSEQ)   // 8192

// Scratch (allocations forbidden)
__device__ float g_Q[(size_t)BBATCH * SSEQ * DDIM];
__device__ float g_K[(size_t)BBATCH * SSEQ * DDIM];
__device__ float g_V[(size_t)BBATCH * SSEQ * DDIM];
__device__ float g_C[(size_t)BBATCH * SSEQ * DDIM];

// ---------------------------------------------------------------------------
// tf32 helpers
// ---------------------------------------------------------------------------
__device__ __forceinline__ unsigned f2tf(float x) {
    unsigned u;
    asm("cvt.rna.tf32.f32 %0, %1;" : "=r"(u) : "f"(x));
    return u;
}

__device__ __forceinline__ void mma_tf32(float* c, const unsigned* a, const unsigned* b) {
    asm volatile(
        "mma.sync.aligned.m16n8k8.row.col.f32.tf32.tf32.f32 "
        "{%0,%1,%2,%3}, {%4,%5,%6,%7}, {%8,%9}, {%0,%1,%2,%3};\n"
        : "+f"(c[0]), "+f"(c[1]), "+f"(c[2]), "+f"(c[3])
        : "r"(a[0]), "r"(a[1]), "r"(a[2]), "r"(a[3]), "r"(b[0]), "r"(b[1]));
}

__device__ __forceinline__ void ldsm4(unsigned* r, const unsigned* p) {
    unsigned addr = (unsigned)__cvta_generic_to_shared(p);
    asm volatile(
        "ldmatrix.sync.aligned.m8n8.x4.shared.b16 {%0,%1,%2,%3}, [%4];\n"
        : "=r"(r[0]), "=r"(r[1]), "=r"(r[2]), "=r"(r[3])
        : "r"(addr));
}

// ---------------------------------------------------------------------------
// Tensor-core GEMM: Y = X @ W^T + bias
//   X: [M,1024] row-major, W: [N,1024] row-major (nn.Linear weight).
//   BM=128, BN=128, BK=32, 256 threads (8 warps, 2x4 -> 64x32 warp tiles).
//   Smem tiles stored k-innermost with row stride 36 words -> ldmatrix
//   conflict-free (row stride = 4 banks; 8 rows x 4-bank spans = 32 banks).
// ---------------------------------------------------------------------------
__global__ void __launch_bounds__(256) gemm_tc(const float* __restrict__ X,
                                               const float* __restrict__ W,
                                               const float* __restrict__ bias,
                                               float* __restrict__ Y,
                                               int headLayout)
{
    __shared__ unsigned As[128 * 36];
    __shared__ unsigned Bs[128 * 36];

    const int tid  = threadIdx.x;
    const int lane = tid & 31;
    const int w    = tid >> 5;
    const int wm0  = (w >> 2) * 64;   // 0 or 64
    const int wn0  = (w & 3) * 32;    // 0,32,64,96
    const int m0   = blockIdx.x * 128;
    const int n0   = blockIdx.y * 128;

    // ldmatrix lane->address offsets (A-operand pattern and B-operand pattern)
    const int mat = lane >> 3, lr = lane & 7;
    const int a_row_off = (mat & 1) * 8 + lr;   // rows 0-15 of a 16x8 A block
    const int a_col_off = (mat >> 1) * 4;       // k 0-3 / 4-7
    const int b_n_off   = (mat >> 1) * 8 + lr;  // 16 n-rows (two 8-n tiles)
    const int b_k_off   = (mat & 1) * 4;        // k 0-3 / 4-7

    // global loader mapping: 4 float4 per thread per matrix
    float4 pa[4], pb[4];
#pragma unroll
    for (int i = 0; i < 4; i++) {
        const int idx = i * 256 + tid;
        const int r = idx >> 3, c = (idx & 7) << 2;
        pa[i] = *(const float4*)(X + (size_t)(m0 + r) * DDIM + c);
        pb[i] = *(const float4*)(W + (size_t)(n0 + r) * DDIM + c);
    }

    float acc[4][4][4];
#pragma unroll
    for (int mt = 0; mt < 4; mt++)
#pragma unroll
        for (int nt = 0; nt < 4; nt++)
#pragma unroll
            for (int j = 0; j < 4; j++) acc[mt][nt][j] = 0.f;

    for (int kt = 0; kt < 32; kt++) {
#pragma unroll
        for (int i = 0; i < 4; i++) {
            const int idx = i * 256 + tid;
            const int r = idx >> 3, c = (idx & 7) << 2;
            uint4 ua = make_uint4(f2tf(pa[i].x), f2tf(pa[i].y), f2tf(pa[i].z), f2tf(pa[i].w));
            uint4 ub = make_uint4(f2tf(pb[i].x), f2tf(pb[i].y), f2tf(pb[i].z), f2tf(pb[i].w));
            *(uint4*)&As[r * 36 + c] = ua;
            *(uint4*)&Bs[r * 36 + c] = ub;
        }
        __syncthreads();

        if (kt < 31) {
            const int koff = (kt + 1) * 32;
#pragma unroll
            for (int i = 0; i < 4; i++) {
                const int idx = i * 256 + tid;
                const int r = idx >> 3, c = (idx & 7) << 2;
                pa[i] = *(const float4*)(X + (size_t)(m0 + r) * DDIM + koff + c);
                pb[i] = *(const float4*)(W + (size_t)(n0 + r) * DDIM + koff + c);
            }
        }

#pragma unroll
        for (int ks = 0; ks < 4; ks++) {
            const int k0 = ks * 8;
            unsigned af[4][4], bf[2][4];
#pragma unroll
            for (int mt = 0; mt < 4; mt++)
                ldsm4(af[mt], &As[(wm0 + mt * 16 + a_row_off) * 36 + k0 + a_col_off]);
#pragma unroll
            for (int p = 0; p < 2; p++)
                ldsm4(bf[p], &Bs[(wn0 + p * 16 + b_n_off) * 36 + k0 + b_k_off]);
#pragma unroll
            for (int mt = 0; mt < 4; mt++)
#pragma unroll
                for (int nt = 0; nt < 4; nt++)
                    mma_tf32(acc[mt][nt], af[mt], &bf[nt >> 1][(nt & 1) * 2]);
        }
        __syncthreads();
    }

    // Epilogue
    const int g = lane >> 2, s2 = (lane & 3) * 2;
#pragma unroll
    for (int mt = 0; mt < 4; mt++) {
#pragma unroll
        for (int nt = 0; nt < 4; nt++) {
            const int col = n0 + wn0 + nt * 8 + s2;
            const float b0 = bias[col], b1 = bias[col + 1];
#pragma unroll
            for (int half = 0; half < 2; half++) {
                const int row = m0 + wm0 + mt * 16 + g + half * 8;
                const float v0 = acc[mt][nt][half * 2 + 0] + b0;
                const float v1 = acc[mt][nt][half * 2 + 1] + b1;
                if (headLayout) {
                    const int b = row / SSEQ, s = row % SSEQ;
                    const int hh = col >> 6, d = col & 63;
                    float* dst = Y + (((size_t)b * HHEADS + hh) * SSEQ + s) * DHEAD + d;
                    dst[0] = v0; dst[1] = v1;
                } else {
                    float* dst = Y + (size_t)row * DDIM + col;
                    dst[0] = v0; dst[1] = v1;
                }
            }
        }
    }
}

// ---------------------------------------------------------------------------
// Flash attention with tf32 tensor cores.
//   Q,K,V: [B*H, S, 64]. One block = (64-row Q tile, bh). 128 threads, 4 warps,
//   warp = 16 rows. Smem row stride 68 words (conflict-free ldmatrix).
// ---------------------------------------------------------------------------
__global__ void __launch_bounds__(128) attn_tc(const float* __restrict__ Q,
                                               const float* __restrict__ K,
                                               const float* __restrict__ V,
                                               float* __restrict__ C)
{
    extern __shared__ unsigned sm[];
    unsigned* Qs = sm;              // [64][68]  rows i,   cols d
    unsigned* Ks = Qs + 64 * 68;    // [64][68]  rows j,   cols d
    unsigned* Vt = Ks + 64 * 68;    // [64][68]  rows d,   cols kpos (transposed)
    unsigned* Ps = Vt + 64 * 68;    // [64][68]  rows i,   cols kpos

    const int tid  = threadIdx.x;
    const int lane = tid & 31;
    const int w    = tid >> 5;
    const int bh   = blockIdx.y;
    const int q0   = blockIdx.x * 64;

    const float* Qb = Q + ((size_t)bh * SSEQ + q0) * DHEAD;
    const float* Kb = K + (size_t)bh * SSEQ * DHEAD;
    const float* Vb = V + (size_t)bh * SSEQ * DHEAD;

    const int mat = lane >> 3, lr = lane & 7;
    const int a_row_off = (mat & 1) * 8 + lr;
    const int a_col_off = (mat >> 1) * 4;
    const int b_n_off   = (mat >> 1) * 8 + lr;
    const int b_k_off   = (mat & 1) * 4;
    const int g = lane >> 2, s2 = (lane & 3) * 2;

    // Load Q tile (tf32)
#pragma unroll
    for (int i = 0; i < 8; i++) {
        const int idx = i * 128 + tid;
        const int r = idx >> 4, c = (idx & 15) << 2;
        float4 qv = *(const float4*)(Qb + (size_t)r * DHEAD + c);
        *(uint4*)&Qs[r * 68 + c] = make_uint4(f2tf(qv.x), f2tf(qv.y), f2tf(qv.z), f2tf(qv.w));
    }

    float o[8][4];
    float m_run[2], l_run[2];
#pragma unroll
    for (int dt = 0; dt < 8; dt++)
#pragma unroll
        for (int j = 0; j < 4; j++) o[dt][j] = 0.f;
    m_run[0] = m_run[1] = -INFINITY;
    l_run[0] = l_run[1] = 0.f;

    const float scale = 0.125f;   // 1/sqrt(64)

    for (int kt = 0; kt < SSEQ / 64; kt++) {
        __syncthreads();   // protect Ks/Vt (prev PV) and Qs (first iter)
        const float* Kp = Kb + (size_t)kt * 64 * DHEAD;
        const float* Vp = Vb + (size_t)kt * 64 * DHEAD;
#pragma unroll
        for (int i = 0; i < 8; i++) {
            const int idx = i * 128 + tid;
            const int r = idx >> 4, c = (idx & 15) << 2;
            float4 kv = *(const float4*)(Kp + (size_t)r * DHEAD + c);
            *(uint4*)&Ks[r * 68 + c] = make_uint4(f2tf(kv.x), f2tf(kv.y), f2tf(kv.z), f2tf(kv.w));
            float4 vv = *(const float4*)(Vp + (size_t)r * DHEAD + c);
            Vt[(c + 0) * 68 + r] = f2tf(vv.x);
            Vt[(c + 1) * 68 + r] = f2tf(vv.y);
            Vt[(c + 2) * 68 + r] = f2tf(vv.z);
            Vt[(c + 3) * 68 + r] = f2tf(vv.w);
        }
        __syncthreads();

        // S = Q @ K^T  (warp: 16 rows x 64 cols)
        float sc[8][4];
#pragma unroll
        for (int nt = 0; nt < 8; nt++)
#pragma unroll
            for (int j = 0; j < 4; j++) sc[nt][j] = 0.f;
#pragma unroll
        for (int ks = 0; ks < 8; ks++) {
            const int k0 = ks * 8;
            unsigned af[4], bf[4][4];
            ldsm4(af, &Qs[(w * 16 + a_row_off) * 68 + k0 + a_col_off]);
#pragma unroll
            for (int p = 0; p < 4; p++)
                ldsm4(bf[p], &Ks[(p * 16 + b_n_off) * 68 + k0 + b_k_off]);
#pragma unroll
            for (int nt = 0; nt < 8; nt++)
                mma_tf32(sc[nt], af, &bf[nt >> 1][(nt & 1) * 2]);
        }

        // Online softmax (row halves: half=0 -> row g, half=1 -> row g+8)
#pragma unroll
        for (int half = 0; half < 2; half++) {
            float mx = -INFINITY;
#pragma unroll
            for (int nt = 0; nt < 8; nt++) {
                mx = fmaxf(mx, sc[nt][half * 2 + 0]);
                mx = fmaxf(mx, sc[nt][half * 2 + 1]);
            }
            mx = fmaxf(mx, __shfl_xor_sync(0xffffffffu, mx, 1));
            mx = fmaxf(mx, __shfl_xor_sync(0xffffffffu, mx, 2));
            const float m_new = fmaxf(m_run[half], mx * scale);
            const float alpha = __expf(m_run[half] - m_new);
            const int prow = (w * 16 + g + half * 8) * 68;
            float rsum = 0.f;
#pragma unroll
            for (int nt = 0; nt < 8; nt++) {
                const float p0 = __expf(sc[nt][half * 2 + 0] * scale - m_new);
                const float p1 = __expf(sc[nt][half * 2 + 1] * scale - m_new);
                rsum += p0 + p1;
                Ps[prow + nt * 8 + s2 + 0] = f2tf(p0);
                Ps[prow + nt * 8 + s2 + 1] = f2tf(p1);
            }
            rsum += __shfl_xor_sync(0xffffffffu, rsum, 1);
            rsum += __shfl_xor_sync(0xffffffffu, rsum, 2);
            l_run[half] = l_run[half] * alpha + rsum;
            m_run[half] = m_new;
#pragma unroll
            for (int dt = 0; dt < 8; dt++) {
                o[dt][half * 2 + 0] *= alpha;
                o[dt][half * 2 + 1] *= alpha;
            }
        }
        __syncthreads();   // Ps visible to ldmatrix

        // O += P @ V   (A = Ps[i][kpos], B = Vt[d][kpos])
#pragma unroll
        for (int ks = 0; ks < 8; ks++) {
            const int k0 = ks * 8;
            unsigned af[4], bf[4][4];
            ldsm4(af, &Ps[(w * 16 + a_row_off) * 68 + k0 + a_col_off]);
#pragma unroll
            for (int p = 0; p < 4; p++)
                ldsm4(bf[p], &Vt[(p * 16 + b_n_off) * 68 + k0 + b_k_off]);
#pragma unroll
            for (int dt = 0; dt < 8; dt++)
                mma_tf32(o[dt], af, &bf[dt >> 1][(dt & 1) * 2]);
        }
    }

    // Normalize + write concat [B,S,D]
    const int b = bh / HHEADS, h = bh % HHEADS;
#pragma unroll
    for (int half = 0; half < 2; half++) {
        const float inv = 1.f / l_run[half];
        const int row = q0 + w * 16 + g + half * 8;
        float* dst = C + ((size_t)b * SSEQ + row) * DDIM + h * DHEAD;
#pragma unroll
        for (int dt = 0; dt < 8; dt++) {
            dst[dt * 8 + s2 + 0] = o[dt][half * 2 + 0] * inv;
            dst[dt * 8 + s2 + 1] = o[dt][half * 2 + 1] * inv;
        }
    }
}

// ---------------------------------------------------------------------------
extern "C" void kernel_launch(void* const* d_in, const int* in_sizes, int n_in,
                              void* d_out, int out_size)
{
    const float* q  = (const float*)d_in[0];
    const float* k  = (const float*)d_in[1];
    const float* v  = (const float*)d_in[2];
    const float* Wq = (const float*)d_in[3];
    const float* bq = (const float*)d_in[4];
    const float* Wk = (const float*)d_in[5];
    const float* bk = (const float*)d_in[6];
    const float* Wv = (const float*)d_in[7];
    const float* bv = (const float*)d_in[8];
    const float* Wo = (const float*)d_in[9];
    const float* bo = (const float*)d_in[10];
    float* out = (float*)d_out;

    float *gQ, *gK, *gV, *gC;
    cudaGetSymbolAddress((void**)&gQ, g_Q);
    cudaGetSymbolAddress((void**)&gK, g_K);
    cudaGetSymbolAddress((void**)&gV, g_V);
    cudaGetSymbolAddress((void**)&gC, g_C);

    const int attn_smem = 4 * 64 * 68 * (int)sizeof(unsigned);  // 69632 B
    cudaFuncSetAttribute(attn_tc, cudaFuncAttributeMaxDynamicSharedMemorySize,
                         attn_smem);

    dim3 gemmGrid(MROWS / 128, DDIM / 128);  // (64, 8)

    gemm_tc<<<gemmGrid, 256>>>(q, Wq, bq, gQ, 1);
    gemm_tc<<<gemmGrid, 256>>>(k, Wk, bk, gK, 1);
    gemm_tc<<<gemmGrid, 256>>>(v, Wv, bv, gV, 1);

    dim3 attnGrid(SSEQ / 64, BBATCH * HHEADS);  // (32, 64)
    attn_tc<<<attnGrid, 128, attn_smem>>>(gQ, gK, gV, gC);

    gemm_tc<<<gemmGrid, 256>>>(gC, Wo, bo, out, 0);
}

// round 3
// speedup vs baseline: 3.5337x; 1.2736x over previous
#include <cuda_runtime.h>
#include <math.h>

#define BBATCH 4
#define SSEQ   2048
#define DDIM   1024
#define HHEADS 16
#define DHEAD  64
#define MROWS  (BBATCH * SSEQ)   // 8192
#define NT_KV  (SSEQ / 64)       // 32

// Scratch (allocations forbidden)
__device__ float g_Q[(size_t)BBATCH * SSEQ * DDIM];  // [bh][s][64], tf32-rounded
__device__ float g_K[(size_t)BBATCH * SSEQ * DDIM];  // [bh][s][64], tf32-rounded
__device__ float g_V[(size_t)BBATCH * SSEQ * DDIM];  // V^T: [bh][64][2048], tf32-rounded
__device__ float g_C[(size_t)BBATCH * SSEQ * DDIM];  // concat, full fp32

// ---------------------------------------------------------------------------
__device__ __forceinline__ unsigned f2tf(float x) {
    unsigned u;
    asm("cvt.rna.tf32.f32 %0, %1;" : "=r"(u) : "f"(x));
    return u;
}

__device__ __forceinline__ void mma_tf32(float* c, const unsigned* a, const unsigned* b) {
    asm volatile(
        "mma.sync.aligned.m16n8k8.row.col.f32.tf32.tf32.f32 "
        "{%0,%1,%2,%3}, {%4,%5,%6,%7}, {%8,%9}, {%0,%1,%2,%3};\n"
        : "+f"(c[0]), "+f"(c[1]), "+f"(c[2]), "+f"(c[3])
        : "r"(a[0]), "r"(a[1]), "r"(a[2]), "r"(a[3]), "r"(b[0]), "r"(b[1]));
}

__device__ __forceinline__ void ldsm4(unsigned* r, const unsigned* p) {
    unsigned addr = (unsigned)__cvta_generic_to_shared(p);
    asm volatile(
        "ldmatrix.sync.aligned.m8n8.x4.shared.b16 {%0,%1,%2,%3}, [%4];\n"
        : "=r"(r[0]), "=r"(r[1]), "=r"(r[2]), "=r"(r[3])
        : "r"(addr));
}

__device__ __forceinline__ void cp16(unsigned saddr, const void* g) {
    asm volatile("cp.async.cg.shared.global [%0], [%1], 16;\n"
                 :: "r"(saddr), "l"(g));
}

// ---------------------------------------------------------------------------
// Tensor-core GEMM: Y = X @ W^T + bias   (same core as round 2)
//   mode 0: Y[m][n] full fp32 (final output)
//   mode 1: Y -> [bh][s][64], tf32-rounded (Q, K)
//   mode 2: Y -> V^T [bh][d][S], tf32-rounded (V)
// ---------------------------------------------------------------------------
__global__ void __launch_bounds__(256) gemm_tc(const float* __restrict__ X,
                                               const float* __restrict__ W,
                                               const float* __restrict__ bias,
                                               float* __restrict__ Y,
                                               int mode)
{
    __shared__ unsigned As[128 * 36];
    __shared__ unsigned Bs[128 * 36];

    const int tid  = threadIdx.x;
    const int lane = tid & 31;
    const int w    = tid >> 5;
    const int wm0  = (w >> 2) * 64;
    const int wn0  = (w & 3) * 32;
    const int m0   = blockIdx.x * 128;
    const int n0   = blockIdx.y * 128;

    const int mat = lane >> 3, lr = lane & 7;
    const int a_row_off = (mat & 1) * 8 + lr;
    const int a_col_off = (mat >> 1) * 4;
    const int b_n_off   = (mat >> 1) * 8 + lr;
    const int b_k_off   = (mat & 1) * 4;

    float4 pa[4], pb[4];
#pragma unroll
    for (int i = 0; i < 4; i++) {
        const int idx = i * 256 + tid;
        const int r = idx >> 3, c = (idx & 7) << 2;
        pa[i] = *(const float4*)(X + (size_t)(m0 + r) * DDIM + c);
        pb[i] = *(const float4*)(W + (size_t)(n0 + r) * DDIM + c);
    }

    float acc[4][4][4];
#pragma unroll
    for (int mt = 0; mt < 4; mt++)
#pragma unroll
        for (int nt = 0; nt < 4; nt++)
#pragma unroll
            for (int j = 0; j < 4; j++) acc[mt][nt][j] = 0.f;

    for (int kt = 0; kt < 32; kt++) {
#pragma unroll
        for (int i = 0; i < 4; i++) {
            const int idx = i * 256 + tid;
            const int r = idx >> 3, c = (idx & 7) << 2;
            uint4 ua = make_uint4(f2tf(pa[i].x), f2tf(pa[i].y), f2tf(pa[i].z), f2tf(pa[i].w));
            uint4 ub = make_uint4(f2tf(pb[i].x), f2tf(pb[i].y), f2tf(pb[i].z), f2tf(pb[i].w));
            *(uint4*)&As[r * 36 + c] = ua;
            *(uint4*)&Bs[r * 36 + c] = ub;
        }
        __syncthreads();

        if (kt < 31) {
            const int koff = (kt + 1) * 32;
#pragma unroll
            for (int i = 0; i < 4; i++) {
                const int idx = i * 256 + tid;
                const int r = idx >> 3, c = (idx & 7) << 2;
                pa[i] = *(const float4*)(X + (size_t)(m0 + r) * DDIM + koff + c);
                pb[i] = *(const float4*)(W + (size_t)(n0 + r) * DDIM + koff + c);
            }
        }

#pragma unroll
        for (int ks = 0; ks < 4; ks++) {
            const int k0 = ks * 8;
            unsigned af[4][4], bf[2][4];
#pragma unroll
            for (int mt = 0; mt < 4; mt++)
                ldsm4(af[mt], &As[(wm0 + mt * 16 + a_row_off) * 36 + k0 + a_col_off]);
#pragma unroll
            for (int p = 0; p < 2; p++)
                ldsm4(bf[p], &Bs[(wn0 + p * 16 + b_n_off) * 36 + k0 + b_k_off]);
#pragma unroll
            for (int mt = 0; mt < 4; mt++)
#pragma unroll
                for (int nt = 0; nt < 4; nt++)
                    mma_tf32(acc[mt][nt], af[mt], &bf[nt >> 1][(nt & 1) * 2]);
        }
        __syncthreads();
    }

    const int g = lane >> 2, s2 = (lane & 3) * 2;
#pragma unroll
    for (int mt = 0; mt < 4; mt++) {
#pragma unroll
        for (int nt = 0; nt < 4; nt++) {
            const int col = n0 + wn0 + nt * 8 + s2;
            const float b0 = bias[col], b1 = bias[col + 1];
#pragma unroll
            for (int half = 0; half < 2; half++) {
                const int row = m0 + wm0 + mt * 16 + g + half * 8;
                const float v0 = acc[mt][nt][half * 2 + 0] + b0;
                const float v1 = acc[mt][nt][half * 2 + 1] + b1;
                if (mode == 1) {
                    const int b = row / SSEQ, s = row % SSEQ;
                    const int hh = col >> 6, d = col & 63;
                    float* dst = Y + (((size_t)b * HHEADS + hh) * SSEQ + s) * DHEAD + d;
                    dst[0] = __uint_as_float(f2tf(v0));
                    dst[1] = __uint_as_float(f2tf(v1));
                } else if (mode == 2) {
                    const int b = row / SSEQ, s = row % SSEQ;
                    const int hh = col >> 6, d = col & 63;
                    float* dst = Y + (((size_t)(b * HHEADS + hh)) * DHEAD + d) * SSEQ + s;
                    dst[0]    = __uint_as_float(f2tf(v0));
                    dst[SSEQ] = __uint_as_float(f2tf(v1));
                } else {
                    float* dst = Y + (size_t)row * DDIM + col;
                    dst[0] = v0; dst[1] = v1;
                }
            }
        }
    }
}

// ---------------------------------------------------------------------------
// Flash attention, tf32 tensor cores, cp.async double-buffered K/V,
// Q fragments hoisted, P kept in registers (C->A via shuffles).
//   Q,K: [bh][s][64] rounded; Vt: [bh][d][2048] rounded.
// smem: 2 stages x (K tile 64x68 + Vt tile 64x68) words = 69632 B.
// ---------------------------------------------------------------------------
__global__ void __launch_bounds__(128) attn_tc(const float* __restrict__ Q,
                                               const float* __restrict__ K,
                                               const float* __restrict__ Vt,
                                               float* __restrict__ C)
{
    extern __shared__ unsigned sm[];
    const int tid  = threadIdx.x;
    const int lane = tid & 31;
    const int w    = tid >> 5;
    const int bh   = blockIdx.y;
    const int q0   = blockIdx.x * 64;

    const float* Qb  = Q  + ((size_t)bh * SSEQ + q0) * DHEAD;
    const float* Kb  = K  + (size_t)bh * SSEQ * DHEAD;
    const float* Vtb = Vt + (size_t)bh * DHEAD * SSEQ;

    const int mat = lane >> 3, lr = lane & 7;
    const int a_row = (mat & 1) * 8 + lr;
    const int a_col = (mat >> 1) * 4;
    const int b_row = (mat >> 1) * 8 + lr;
    const int b_col = (mat & 1) * 4;
    const int g = lane >> 2, t = lane & 3, s2 = t * 2;

    const int rr = tid >> 4;            // 0..7 loader row base
    const int cc = (tid & 15) << 2;     // 0..60 loader col (words)

    const unsigned smbase = (unsigned)__cvta_generic_to_shared(sm);

    // ---- prologue: stage 0 in flight, Q staged through stage-1 K region ----
    {
        const float* kg = Kb;
        const float* vg = Vtb;
        unsigned kdst = smbase;
        unsigned vdst = smbase + 4352u * 4u;
#pragma unroll
        for (int i = 0; i < 8; i++) {
            const int r2 = i * 8 + rr;
            cp16(kdst + (unsigned)(r2 * 68 + cc) * 4u, kg + (size_t)r2 * DHEAD + cc);
            cp16(vdst + (unsigned)(r2 * 68 + cc) * 4u, vg + (size_t)r2 * SSEQ + cc);
        }
        asm volatile("cp.async.commit_group;\n");
    }
    unsigned* Qs = sm + 8704;   // stage-1 K region, free until kt=0 issues stage 1
#pragma unroll
    for (int i = 0; i < 8; i++) {
        const int r2 = i * 8 + rr;
        float4 qv = *(const float4*)(Qb + (size_t)r2 * DHEAD + cc);
        *(uint4*)&Qs[r2 * 68 + cc] = *(uint4*)&qv;   // already tf32-rounded bits
    }
    __syncthreads();
    unsigned aq[8][4];
#pragma unroll
    for (int ks = 0; ks < 8; ks++)
        ldsm4(aq[ks], &Qs[(w * 16 + a_row) * 68 + ks * 8 + a_col]);

    float o[8][4];
#pragma unroll
    for (int dt = 0; dt < 8; dt++)
#pragma unroll
        for (int j = 0; j < 4; j++) o[dt][j] = 0.f;
    float m0 = -INFINITY, m1 = -INFINITY, l0 = 0.f, l1 = 0.f;
    const float scale = 0.125f;
    const int shbase = (lane & ~3) | (t >> 1);

    for (int kt = 0; kt < NT_KV; kt++) {
        __syncthreads();   // all warps done with previous tile's smem reads
        if (kt + 1 < NT_KV) {
            const int s = (kt + 1) & 1;
            unsigned kdst = smbase + (unsigned)(s * 8704) * 4u;
            unsigned vdst = kdst + 4352u * 4u;
            const float* kg = Kb + (size_t)(kt + 1) * 64 * DHEAD;
            const float* vg = Vtb + (kt + 1) * 64;
#pragma unroll
            for (int i = 0; i < 8; i++) {
                const int r2 = i * 8 + rr;
                cp16(kdst + (unsigned)(r2 * 68 + cc) * 4u, kg + (size_t)r2 * DHEAD + cc);
                cp16(vdst + (unsigned)(r2 * 68 + cc) * 4u, vg + (size_t)r2 * SSEQ + cc);
            }
            asm volatile("cp.async.commit_group;\n");
            asm volatile("cp.async.wait_group 1;\n");
        } else {
            asm volatile("cp.async.wait_group 0;\n");
        }
        __syncthreads();   // current stage visible to all warps

        const unsigned* Ks = sm + (kt & 1) * 8704;
        const unsigned* Vs = Ks + 4352;

        // ---- S = Q @ K^T ----
        float sc[8][4];
#pragma unroll
        for (int nt = 0; nt < 8; nt++)
#pragma unroll
            for (int j = 0; j < 4; j++) sc[nt][j] = 0.f;
#pragma unroll
        for (int ks = 0; ks < 8; ks++) {
            unsigned bf[4][4];
#pragma unroll
            for (int p = 0; p < 4; p++)
                ldsm4(bf[p], &Ks[(p * 16 + b_row) * 68 + ks * 8 + b_col]);
#pragma unroll
            for (int nt = 0; nt < 8; nt++)
                mma_tf32(sc[nt], aq[ks], &bf[nt >> 1][(nt & 1) * 2]);
        }

        // ---- online softmax (rows g and g+8), P kept in registers ----
        float mx0 = -INFINITY, mx1 = -INFINITY;
#pragma unroll
        for (int nt = 0; nt < 8; nt++) {
            mx0 = fmaxf(mx0, fmaxf(sc[nt][0], sc[nt][1]));
            mx1 = fmaxf(mx1, fmaxf(sc[nt][2], sc[nt][3]));
        }
        mx0 = fmaxf(mx0, __shfl_xor_sync(0xffffffffu, mx0, 1));
        mx0 = fmaxf(mx0, __shfl_xor_sync(0xffffffffu, mx0, 2));
        mx1 = fmaxf(mx1, __shfl_xor_sync(0xffffffffu, mx1, 1));
        mx1 = fmaxf(mx1, __shfl_xor_sync(0xffffffffu, mx1, 2));
        const float mn0 = fmaxf(m0, mx0 * scale);
        const float mn1 = fmaxf(m1, mx1 * scale);
        const float al0 = __expf(m0 - mn0);
        const float al1 = __expf(m1 - mn1);

        float rs0 = 0.f, rs1 = 0.f;
        unsigned ap[8][4];
        const bool odd = (t & 1);
#pragma unroll
        for (int nt = 0; nt < 8; nt++) {
            const float e0 = __expf(sc[nt][0] * scale - mn0);
            const float e1 = __expf(sc[nt][1] * scale - mn0);
            const float e2 = __expf(sc[nt][2] * scale - mn1);
            const float e3 = __expf(sc[nt][3] * scale - mn1);
            rs0 += e0 + e1;
            rs1 += e2 + e3;
            const unsigned u0 = f2tf(e0), u1 = f2tf(e1), u2 = f2tf(e2), u3 = f2tf(e3);
            // C-fragment -> A-fragment permutation:
            //   a0=P[g][t], a1=P[g+8][t], a2=P[g][t+4], a3=P[g+8][t+4]
            const unsigned x0 = __shfl_sync(0xffffffffu, u0, shbase);
            const unsigned x1 = __shfl_sync(0xffffffffu, u1, shbase);
            const unsigned x2 = __shfl_sync(0xffffffffu, u2, shbase);
            const unsigned x3 = __shfl_sync(0xffffffffu, u3, shbase);
            const unsigned y0 = __shfl_sync(0xffffffffu, u0, shbase + 2);
            const unsigned y1 = __shfl_sync(0xffffffffu, u1, shbase + 2);
            const unsigned y2 = __shfl_sync(0xffffffffu, u2, shbase + 2);
            const unsigned y3 = __shfl_sync(0xffffffffu, u3, shbase + 2);
            ap[nt][0] = odd ? x1 : x0;
            ap[nt][1] = odd ? x3 : x2;
            ap[nt][2] = odd ? y1 : y0;
            ap[nt][3] = odd ? y3 : y2;
        }
        rs0 += __shfl_xor_sync(0xffffffffu, rs0, 1);
        rs0 += __shfl_xor_sync(0xffffffffu, rs0, 2);
        rs1 += __shfl_xor_sync(0xffffffffu, rs1, 1);
        rs1 += __shfl_xor_sync(0xffffffffu, rs1, 2);
        l0 = l0 * al0 + rs0;
        l1 = l1 * al1 + rs1;
        m0 = mn0; m1 = mn1;
#pragma unroll
        for (int dt = 0; dt < 8; dt++) {
            o[dt][0] *= al0; o[dt][1] *= al0;
            o[dt][2] *= al1; o[dt][3] *= al1;
        }

        // ---- O += P @ V  (B from Vt[d][kpos]) ----
#pragma unroll
        for (int ks = 0; ks < 8; ks++) {
            unsigned bf[4][4];
#pragma unroll
            for (int p = 0; p < 4; p++)
                ldsm4(bf[p], &Vs[(p * 16 + b_row) * 68 + ks * 8 + b_col]);
#pragma unroll
            for (int dt = 0; dt < 8; dt++)
                mma_tf32(o[dt], ap[ks], &bf[dt >> 1][(dt & 1) * 2]);
        }
    }

    // ---- normalize + write concat [B,S,D] ----
    const int b = bh / HHEADS, h = bh % HHEADS;
    const float inv0 = 1.f / l0, inv1 = 1.f / l1;
    const int row0 = q0 + w * 16 + g;
    float* d0 = C + ((size_t)b * SSEQ + row0) * DDIM + h * DHEAD;
    float* d1 = C + ((size_t)b * SSEQ + row0 + 8) * DDIM + h * DHEAD;
#pragma unroll
    for (int dt = 0; dt < 8; dt++) {
        d0[dt * 8 + s2 + 0] = o[dt][0] * inv0;
        d0[dt * 8 + s2 + 1] = o[dt][1] * inv0;
        d1[dt * 8 + s2 + 0] = o[dt][2] * inv1;
        d1[dt * 8 + s2 + 1] = o[dt][3] * inv1;
    }
}

// ---------------------------------------------------------------------------
extern "C" void kernel_launch(void* const* d_in, const int* in_sizes, int n_in,
                              void* d_out, int out_size)
{
    const float* q  = (const float*)d_in[0];
    const float* k  = (const float*)d_in[1];
    const float* v  = (const float*)d_in[2];
    const float* Wq = (const float*)d_in[3];
    const float* bq = (const float*)d_in[4];
    const float* Wk = (const float*)d_in[5];
    const float* bk = (const float*)d_in[6];
    const float* Wv = (const float*)d_in[7];
    const float* bv = (const float*)d_in[8];
    const float* Wo = (const float*)d_in[9];
    const float* bo = (const float*)d_in[10];
    float* out = (float*)d_out;

    float *gQ, *gK, *gV, *gC;
    cudaGetSymbolAddress((void**)&gQ, g_Q);
    cudaGetSymbolAddress((void**)&gK, g_K);
    cudaGetSymbolAddress((void**)&gV, g_V);
    cudaGetSymbolAddress((void**)&gC, g_C);

    const int attn_smem = 4 * 64 * 68 * (int)sizeof(unsigned);  // 69632 B
    cudaFuncSetAttribute(attn_tc, cudaFuncAttributeMaxDynamicSharedMemorySize,
                         attn_smem);

    dim3 gemmGrid(MROWS / 128, DDIM / 128);  // (64, 8)

    gemm_tc<<<gemmGrid, 256>>>(q, Wq, bq, gQ, 1);
    gemm_tc<<<gemmGrid, 256>>>(k, Wk, bk, gK, 1);
    gemm_tc<<<gemmGrid, 256>>>(v, Wv, bv, gV, 2);   // writes V^T

    dim3 attnGrid(SSEQ / 64, BBATCH * HHEADS);  // (32, 64)
    attn_tc<<<attnGrid, 128, attn_smem>>>(gQ, gK, gV, gC);

    gemm_tc<<<gemmGrid, 256>>>(gC, Wo, bo, out, 0);
}

// round 5
// speedup vs baseline: 4.1028x; 1.1611x over previous
#include <cuda_runtime.h>
#include <math.h>
#include <stdint.h>

#define BBATCH 4
#define SSEQ   2048
#define DDIM   1024
#define HHEADS 16
#define DHEAD  64
#define MROWS  (BBATCH * SSEQ)   // 8192
#define NT_KV  (SSEQ / 64)       // 32

// Scratch (allocations forbidden)
__device__ float g_Q[(size_t)BBATCH * SSEQ * DDIM];  // [bh][s][64], tf32-rounded bits
__device__ float g_K[(size_t)BBATCH * SSEQ * DDIM];  // [bh][s][64], tf32-rounded bits
__device__ float g_V[(size_t)BBATCH * SSEQ * DDIM];  // V^T: [bh][64][2048], tf32 bits
__device__ float g_C[(size_t)BBATCH * SSEQ * DDIM];  // concat, tf32-rounded bits
__device__ float g_Xr[(size_t)MROWS * DDIM];         // rounded activation staging
__device__ float g_Wr[(size_t)4 * DDIM * DDIM];      // rounded weights Wq,Wk,Wv,Wo

// ---------------------------------------------------------------------------
__device__ __forceinline__ unsigned f2tf(float x) {
    unsigned u;
    asm("cvt.rna.tf32.f32 %0, %1;" : "=r"(u) : "f"(x));
    return u;
}
__device__ __forceinline__ void mma_tf32(float* c, const unsigned* a, const unsigned* b) {
    asm volatile(
        "mma.sync.aligned.m16n8k8.row.col.f32.tf32.tf32.f32 "
        "{%0,%1,%2,%3}, {%4,%5,%6,%7}, {%8,%9}, {%0,%1,%2,%3};\n"
        : "+f"(c[0]), "+f"(c[1]), "+f"(c[2]), "+f"(c[3])
        : "r"(a[0]), "r"(a[1]), "r"(a[2]), "r"(a[3]), "r"(b[0]), "r"(b[1]));
}
__device__ __forceinline__ void ldsm4(unsigned* r, const unsigned* p) {
    unsigned addr = (unsigned)__cvta_generic_to_shared(p);
    asm volatile(
        "ldmatrix.sync.aligned.m8n8.x4.shared.b16 {%0,%1,%2,%3}, [%4];\n"
        : "=r"(r[0]), "=r"(r[1]), "=r"(r[2]), "=r"(r[3])
        : "r"(addr));
}
__device__ __forceinline__ void cp16(unsigned saddr, const void* g) {
    asm volatile("cp.async.cg.shared.global [%0], [%1], 16;\n"
                 :: "r"(saddr), "l"(g));
}

// ---------------------------------------------------------------------------
// Elementwise tf32 rounding pass (fp32 -> tf32-bits-in-fp32)
// ---------------------------------------------------------------------------
__global__ void __launch_bounds__(256) round_tf32(const float* __restrict__ src,
                                                  float* __restrict__ dst, int n)
{
    const int i = (blockIdx.x * 256 + threadIdx.x) * 4;
    if (i >= n) return;
    float4 x = *(const float4*)(src + i);
    uint4 u = make_uint4(f2tf(x.x), f2tf(x.y), f2tf(x.z), f2tf(x.w));
    *(uint4*)(dst + i) = u;
}

// ---------------------------------------------------------------------------
// tf32 GEMM, cp.async 3-stage pipeline: Y = X @ W^T + bias
//   Inputs already tf32-rounded bits. BM=BN=128, BK=32, 256 threads (8 warps,
//   2x4 -> 64x32 warp tiles). Smem rows stride 36 words (ldsm conflict-free).
//   Stage = A(128x36) + B(128x36) words = 36864 B; 3 stages = 110592 B.
//   mode 0: plain fp32 out; 1: [bh][s][64] rounded; 2: V^T [bh][d][S] rounded.
// ---------------------------------------------------------------------------
__global__ void __launch_bounds__(256) gemm_p(const float* __restrict__ X,
                                              const float* __restrict__ W,
                                              const float* __restrict__ bias,
                                              float* __restrict__ Y,
                                              int mode)
{
    extern __shared__ unsigned smem[];
    const unsigned smbase = (unsigned)__cvta_generic_to_shared(smem);

    const int tid  = threadIdx.x;
    const int lane = tid & 31;
    const int w    = tid >> 5;
    const int wm0  = (w >> 2) * 64;
    const int wn0  = (w & 3) * 32;
    const int m0   = blockIdx.x * 128;
    const int n0   = blockIdx.y * 128;

    const int mat = lane >> 3, lr = lane & 7;
    const int a_row_off = (mat & 1) * 8 + lr;
    const int a_col_off = (mat >> 1) * 4;
    const int b_n_off   = (mat >> 1) * 8 + lr;
    const int b_k_off   = (mat & 1) * 4;

#define GLOADG(kc, buf)                                                        \
    {                                                                          \
        const unsigned sb = smbase + (unsigned)(buf) * 36864u;                 \
        const int kco = (kc) * 32;                                             \
        _Pragma("unroll")                                                      \
        for (int i = 0; i < 4; i++) {                                          \
            const int chunk = i * 256 + tid;                                   \
            const int r = chunk >> 3, j = (chunk & 7) << 2;                    \
            const unsigned off = (unsigned)(r * 36 + j) * 4u;                  \
            cp16(sb + off,          X + (size_t)(m0 + r) * DDIM + kco + j);    \
            cp16(sb + 18432u + off, W + (size_t)(n0 + r) * DDIM + kco + j);    \
        }                                                                      \
        asm volatile("cp.async.commit_group;\n");                              \
    }

    GLOADG(0, 0);
    GLOADG(1, 1);
    GLOADG(2, 2);

    float acc[4][4][4];
#pragma unroll
    for (int mt = 0; mt < 4; mt++)
#pragma unroll
        for (int nt = 0; nt < 4; nt++)
#pragma unroll
            for (int j = 0; j < 4; j++) acc[mt][nt][j] = 0.f;

    int buf = 0;
    for (int kt = 0; kt < 32; kt++) {
        if (kt <= 29)       asm volatile("cp.async.wait_group 2;\n");
        else if (kt == 30)  asm volatile("cp.async.wait_group 1;\n");
        else                asm volatile("cp.async.wait_group 0;\n");
        __syncthreads();

        const unsigned* As = smem + buf * 9216;
        const unsigned* Bs = As + 4608;
#pragma unroll
        for (int ks = 0; ks < 4; ks++) {
            const int k0 = ks * 8;
            unsigned af[4][4], bf[2][4];
#pragma unroll
            for (int mt = 0; mt < 4; mt++)
                ldsm4(af[mt], &As[(wm0 + mt * 16 + a_row_off) * 36 + k0 + a_col_off]);
#pragma unroll
            for (int p = 0; p < 2; p++)
                ldsm4(bf[p], &Bs[(wn0 + p * 16 + b_n_off) * 36 + k0 + b_k_off]);
#pragma unroll
            for (int mt = 0; mt < 4; mt++)
#pragma unroll
                for (int nt = 0; nt < 4; nt++)
                    mma_tf32(acc[mt][nt], af[mt], &bf[nt >> 1][(nt & 1) * 2]);
        }
        __syncthreads();

        if (kt + 3 < 32) GLOADG(kt + 3, buf);
        buf = (buf == 2) ? 0 : buf + 1;
    }
#undef GLOADG

    const int g = lane >> 2, s2 = (lane & 3) * 2;
#pragma unroll
    for (int mt = 0; mt < 4; mt++) {
#pragma unroll
        for (int nt = 0; nt < 4; nt++) {
            const int col = n0 + wn0 + nt * 8 + s2;
            const float b0 = bias[col], b1 = bias[col + 1];
#pragma unroll
            for (int half = 0; half < 2; half++) {
                const int row = m0 + wm0 + mt * 16 + g + half * 8;
                const float v0 = acc[mt][nt][half * 2 + 0] + b0;
                const float v1 = acc[mt][nt][half * 2 + 1] + b1;
                if (mode == 1) {
                    const int b = row >> 11, s = row & 2047;
                    const int hh = col >> 6, d = col & 63;
                    float* dst = Y + (((size_t)b * HHEADS + hh) * SSEQ + s) * DHEAD + d;
                    dst[0] = __uint_as_float(f2tf(v0));
                    dst[1] = __uint_as_float(f2tf(v1));
                } else if (mode == 2) {
                    const int b = row >> 11, s = row & 2047;
                    const int hh = col >> 6, d = col & 63;
                    float* dst = Y + (((size_t)(b * HHEADS + hh)) * DHEAD + d) * SSEQ + s;
                    dst[0]    = __uint_as_float(f2tf(v0));
                    dst[SSEQ] = __uint_as_float(f2tf(v1));
                } else {
                    float* dst = Y + (size_t)row * DDIM + col;
                    dst[0] = v0; dst[1] = v1;
                }
            }
        }
    }
}

// ---------------------------------------------------------------------------
// Flash attention, tf32 mma.sync. 256 threads / 8 warps / 128 Q rows per CTA.
//   Q fragments loaded directly from global (pre-rounded bits).
//   K/V cp.async double-buffered (2 x (K 64x68 + V^T 64x68) words = 69632 B).
//   P kept in registers via C->A shuffle permutation. C written tf32-rounded.
// ---------------------------------------------------------------------------
__global__ void __launch_bounds__(256, 2) attn_tc(const float* __restrict__ Q,
                                                  const float* __restrict__ K,
                                                  const float* __restrict__ Vt,
                                                  float* __restrict__ C)
{
    extern __shared__ unsigned sm[];
    const int tid  = threadIdx.x;
    const int lane = tid & 31;
    const int w    = tid >> 5;       // 0..7, warp w -> rows w*16..w*16+15
    const int bh   = blockIdx.y;
    const int q0   = blockIdx.x * 128;

    const float* Kb  = K  + (size_t)bh * SSEQ * DHEAD;
    const float* Vtb = Vt + (size_t)bh * DHEAD * SSEQ;

    const int mat = lane >> 3, lr = lane & 7;
    const int b_row = (mat >> 1) * 8 + lr;
    const int b_col = (mat & 1) * 4;
    const int g = lane >> 2, t = lane & 3, s2 = t * 2;

    const int rr = tid >> 4;            // 0..15 loader row base
    const int cc = (tid & 15) << 2;     // 0..60 loader col (words)

    const unsigned smbase = (unsigned)__cvta_generic_to_shared(sm);

    // ---- prologue: stage 0 K/V in flight ----
    {
        unsigned kdst = smbase;
        unsigned vdst = smbase + 4352u * 4u;
#pragma unroll
        for (int i = 0; i < 4; i++) {
            const int r2 = i * 16 + rr;
            cp16(kdst + (unsigned)(r2 * 68 + cc) * 4u, Kb + (size_t)r2 * DHEAD + cc);
            cp16(vdst + (unsigned)(r2 * 68 + cc) * 4u, Vtb + (size_t)r2 * SSEQ + cc);
        }
        asm volatile("cp.async.commit_group;\n");
    }

    // ---- Q fragments straight from global (tf32 bits) ----
    unsigned aq[8][4];
    {
        const float* Qw = Q + ((size_t)bh * SSEQ + q0 + w * 16) * DHEAD;
#pragma unroll
        for (int ks = 0; ks < 8; ks++) {
            const int c0 = ks * 8 + t;
            aq[ks][0] = __float_as_uint(Qw[(size_t)g * DHEAD + c0]);
            aq[ks][1] = __float_as_uint(Qw[(size_t)(g + 8) * DHEAD + c0]);
            aq[ks][2] = __float_as_uint(Qw[(size_t)g * DHEAD + c0 + 4]);
            aq[ks][3] = __float_as_uint(Qw[(size_t)(g + 8) * DHEAD + c0 + 4]);
        }
    }

    float o[8][4];
#pragma unroll
    for (int dt = 0; dt < 8; dt++)
#pragma unroll
        for (int j = 0; j < 4; j++) o[dt][j] = 0.f;
    float m0 = -INFINITY, m1 = -INFINITY, l0 = 0.f, l1 = 0.f;
    const float scale = 0.125f;
    const int shbase = (lane & ~3) | (t >> 1);

    for (int kt = 0; kt < NT_KV; kt++) {
        __syncthreads();
        if (kt + 1 < NT_KV) {
            const int s = (kt + 1) & 1;
            unsigned kdst = smbase + (unsigned)(s * 8704) * 4u;
            unsigned vdst = kdst + 4352u * 4u;
            const float* kg = Kb + (size_t)(kt + 1) * 64 * DHEAD;
            const float* vg = Vtb + (kt + 1) * 64;
#pragma unroll
            for (int i = 0; i < 4; i++) {
                const int r2 = i * 16 + rr;
                cp16(kdst + (unsigned)(r2 * 68 + cc) * 4u, kg + (size_t)r2 * DHEAD + cc);
                cp16(vdst + (unsigned)(r2 * 68 + cc) * 4u, vg + (size_t)r2 * SSEQ + cc);
            }
            asm volatile("cp.async.commit_group;\n");
            asm volatile("cp.async.wait_group 1;\n");
        } else {
            asm volatile("cp.async.wait_group 0;\n");
        }
        __syncthreads();

        const unsigned* Ks = sm + (kt & 1) * 8704;
        const unsigned* Vs = Ks + 4352;

        // ---- S = Q @ K^T ----
        float sc[8][4];
#pragma unroll
        for (int nt = 0; nt < 8; nt++)
#pragma unroll
            for (int j = 0; j < 4; j++) sc[nt][j] = 0.f;
#pragma unroll
        for (int ks = 0; ks < 8; ks++) {
            unsigned bf[4][4];
#pragma unroll
            for (int p = 0; p < 4; p++)
                ldsm4(bf[p], &Ks[(p * 16 + b_row) * 68 + ks * 8 + b_col]);
#pragma unroll
            for (int nt = 0; nt < 8; nt++)
                mma_tf32(sc[nt], aq[ks], &bf[nt >> 1][(nt & 1) * 2]);
        }

        // ---- online softmax, P in registers ----
        float mx0 = -INFINITY, mx1 = -INFINITY;
#pragma unroll
        for (int nt = 0; nt < 8; nt++) {
            mx0 = fmaxf(mx0, fmaxf(sc[nt][0], sc[nt][1]));
            mx1 = fmaxf(mx1, fmaxf(sc[nt][2], sc[nt][3]));
        }
        mx0 = fmaxf(mx0, __shfl_xor_sync(0xffffffffu, mx0, 1));
        mx0 = fmaxf(mx0, __shfl_xor_sync(0xffffffffu, mx0, 2));
        mx1 = fmaxf(mx1, __shfl_xor_sync(0xffffffffu, mx1, 1));
        mx1 = fmaxf(mx1, __shfl_xor_sync(0xffffffffu, mx1, 2));
        const float mn0 = fmaxf(m0, mx0 * scale);
        const float mn1 = fmaxf(m1, mx1 * scale);
        const float al0 = __expf(m0 - mn0);
        const float al1 = __expf(m1 - mn1);

        float rs0 = 0.f, rs1 = 0.f;
        unsigned ap[8][4];
        const bool odd = (t & 1);
#pragma unroll
        for (int nt = 0; nt < 8; nt++) {
            const float e0 = __expf(sc[nt][0] * scale - mn0);
            const float e1 = __expf(sc[nt][1] * scale - mn0);
            const float e2 = __expf(sc[nt][2] * scale - mn1);
            const float e3 = __expf(sc[nt][3] * scale - mn1);
            rs0 += e0 + e1;
            rs1 += e2 + e3;
            const unsigned u0 = f2tf(e0), u1 = f2tf(e1), u2 = f2tf(e2), u3 = f2tf(e3);
            const unsigned x0 = __shfl_sync(0xffffffffu, u0, shbase);
            const unsigned x1 = __shfl_sync(0xffffffffu, u1, shbase);
            const unsigned x2 = __shfl_sync(0xffffffffu, u2, shbase);
            const unsigned x3 = __shfl_sync(0xffffffffu, u3, shbase);
            const unsigned y0 = __shfl_sync(0xffffffffu, u0, shbase + 2);
            const unsigned y1 = __shfl_sync(0xffffffffu, u1, shbase + 2);
            const unsigned y2 = __shfl_sync(0xffffffffu, u2, shbase + 2);
            const unsigned y3 = __shfl_sync(0xffffffffu, u3, shbase + 2);
            ap[nt][0] = odd ? x1 : x0;
            ap[nt][1] = odd ? x3 : x2;
            ap[nt][2] = odd ? y1 : y0;
            ap[nt][3] = odd ? y3 : y2;
        }
        rs0 += __shfl_xor_sync(0xffffffffu, rs0, 1);
        rs0 += __shfl_xor_sync(0xffffffffu, rs0, 2);
        rs1 += __shfl_xor_sync(0xffffffffu, rs1, 1);
        rs1 += __shfl_xor_sync(0xffffffffu, rs1, 2);
        l0 = l0 * al0 + rs0;
        l1 = l1 * al1 + rs1;
        m0 = mn0; m1 = mn1;
#pragma unroll
        for (int dt = 0; dt < 8; dt++) {
            o[dt][0] *= al0; o[dt][1] *= al0;
            o[dt][2] *= al1; o[dt][3] *= al1;
        }

        // ---- O += P @ V ----
#pragma unroll
        for (int ks = 0; ks < 8; ks++) {
            unsigned bf[4][4];
#pragma unroll
            for (int p = 0; p < 4; p++)
                ldsm4(bf[p], &Vs[(p * 16 + b_row) * 68 + ks * 8 + b_col]);
#pragma unroll
            for (int dt = 0; dt < 8; dt++)
                mma_tf32(o[dt], ap[ks], &bf[dt >> 1][(dt & 1) * 2]);
        }
    }

    // ---- normalize + write concat [B,S,D], tf32-rounded ----
    const int b = bh / HHEADS, h = bh % HHEADS;
    const float inv0 = 1.f / l0, inv1 = 1.f / l1;
    const int row0 = q0 + w * 16 + g;
    float* d0 = C + ((size_t)b * SSEQ + row0) * DDIM + h * DHEAD;
    float* d1 = C + ((size_t)b * SSEQ + row0 + 8) * DDIM + h * DHEAD;
#pragma unroll
    for (int dt = 0; dt < 8; dt++) {
        d0[dt * 8 + s2 + 0] = __uint_as_float(f2tf(o[dt][0] * inv0));
        d0[dt * 8 + s2 + 1] = __uint_as_float(f2tf(o[dt][1] * inv0));
        d1[dt * 8 + s2 + 0] = __uint_as_float(f2tf(o[dt][2] * inv1));
        d1[dt * 8 + s2 + 1] = __uint_as_float(f2tf(o[dt][3] * inv1));
    }
}

// ---------------------------------------------------------------------------
extern "C" void kernel_launch(void* const* d_in, const int* in_sizes, int n_in,
                              void* d_out, int out_size)
{
    const float* q  = (const float*)d_in[0];
    const float* k  = (const float*)d_in[1];
    const float* v  = (const float*)d_in[2];
    const float* Wq = (const float*)d_in[3];
    const float* bq = (const float*)d_in[4];
    const float* Wk = (const float*)d_in[5];
    const float* bk = (const float*)d_in[6];
    const float* Wv = (const float*)d_in[7];
    const float* bv = (const float*)d_in[8];
    const float* Wo = (const float*)d_in[9];
    const float* bo = (const float*)d_in[10];
    float* out = (float*)d_out;

    float *gQ, *gK, *gV, *gC, *gXr, *gWr;
    cudaGetSymbolAddress((void**)&gQ, g_Q);
    cudaGetSymbolAddress((void**)&gK, g_K);
    cudaGetSymbolAddress((void**)&gV, g_V);
    cudaGetSymbolAddress((void**)&gC, g_C);
    cudaGetSymbolAddress((void**)&gXr, g_Xr);
    cudaGetSymbolAddress((void**)&gWr, g_Wr);

    const int attn_smem = 4 * 64 * 68 * (int)sizeof(unsigned);  // 69632 B
    cudaFuncSetAttribute(attn_tc, cudaFuncAttributeMaxDynamicSharedMemorySize,
                         attn_smem);
    const int gemm_smem = 3 * 2 * 128 * 36 * (int)sizeof(unsigned);  // 110592 B
    cudaFuncSetAttribute(gemm_p, cudaFuncAttributeMaxDynamicSharedMemorySize,
                         gemm_smem);

    const int NW = DDIM * DDIM;      // 1048576
    const int NX = MROWS * DDIM;     // 8388608
    const size_t WOFF = (size_t)NW;

    // round weights once
    round_tf32<<<NW / 1024, 256>>>(Wq, gWr + 0 * WOFF, NW);
    round_tf32<<<NW / 1024, 256>>>(Wk, gWr + 1 * WOFF, NW);
    round_tf32<<<NW / 1024, 256>>>(Wv, gWr + 2 * WOFF, NW);
    round_tf32<<<NW / 1024, 256>>>(Wo, gWr + 3 * WOFF, NW);

    dim3 gemmGrid(MROWS / 128, DDIM / 128);  // (64, 8)

    round_tf32<<<NX / 1024, 256>>>(q, gXr, NX);
    gemm_p<<<gemmGrid, 256, gemm_smem>>>(gXr, gWr + 0 * WOFF, bq, gQ, 1);
    round_tf32<<<NX / 1024, 256>>>(k, gXr, NX);
    gemm_p<<<gemmGrid, 256, gemm_smem>>>(gXr, gWr + 1 * WOFF, bk, gK, 1);
    round_tf32<<<NX / 1024, 256>>>(v, gXr, NX);
    gemm_p<<<gemmGrid, 256, gemm_smem>>>(gXr, gWr + 2 * WOFF, bv, gV, 2);

    dim3 attnGrid(SSEQ / 128, BBATCH * HHEADS);  // (16, 64)
    attn_tc<<<attnGrid, 256, attn_smem>>>(gQ, gK, gV, gC);

    // C is already tf32-rounded by attn epilogue
    gemm_p<<<gemmGrid, 256, gemm_smem>>>(gC, gWr + 3 * WOFF, bo, out, 0);
}